// round 1
// baseline (speedup 1.0000x reference)
#include <cuda_runtime.h>

#define CEPS 1e-3f

// scratch (allocation-free rule: __device__ globals)
__device__ float g_y0[100000 * 16];
__device__ float g_y1[100000 * 16];
__device__ float g_merged[200000 * 16];
__device__ float g_stats[64];   // [0:16) sum0, [16:32) sq0, [32:48) sum1, [48:64) sq1
__device__ float g_aff[64];     // [0:16) s0, [16:32) t0, [32:48) s1, [48:64) t1

// ---------------------------------------------------------------------------
// Submanifold 3x3x3 conv: y[n,o] = sum_k sum_c x[nbr[n,k],c] * W[k,c,o]
// Block: 256 threads -> 128 rows x 16 out-ch.  Thread: 8 rows x 1 ch.
// LAYER==1 applies BN(aff base 0)+ReLU to gathered values on the fly.
// Epilogue accumulates per-channel sum / sumsq into g_stats.
// ---------------------------------------------------------------------------
template <int LAYER>
__global__ __launch_bounds__(256) void conv_kernel(
    const float* __restrict__ x, const int* __restrict__ nbr,
    const float* __restrict__ W, float* __restrict__ y, int N)
{
    __shared__ float Ws[27 * 256];      // [k][c][o]
    __shared__ float xs[16 * 132];      // transposed gather tile [c][row], padded
    __shared__ float saff[32];

    int tid = threadIdx.x;
    for (int i = tid; i < 27 * 256; i += 256) Ws[i] = W[i];
    if (LAYER == 1 && tid < 32) saff[tid] = g_aff[tid];

    int tx = tid & 15;    // output channel
    int ty = tid >> 4;    // row group (8 rows)
    int row0 = blockIdx.x * 128;

    float acc[8];
#pragma unroll
    for (int j = 0; j < 8; j++) acc[j] = 0.f;
    __syncthreads();

    for (int k = 0; k < 27; k++) {
        // ---- stage gathered neighbor tile (transposed) ----
#pragma unroll
        for (int i = 0; i < 2; i++) {
            int e  = tid + i * 256;     // 0..511 -> (row, c-quad)
            int r  = e >> 2;            // 0..127
            int c4 = (e & 3) * 4;
            int gr = row0 + r;
            int id = (gr < N) ? nbr[gr * 27 + k] : -1;
            float4 v = make_float4(0.f, 0.f, 0.f, 0.f);
            if (id >= 0) {
                v = *(const float4*)(x + id * 16 + c4);
                if (LAYER == 1) {
                    v.x = fmaxf(fmaf(v.x, saff[c4 + 0], saff[16 + c4 + 0]), 0.f);
                    v.y = fmaxf(fmaf(v.y, saff[c4 + 1], saff[16 + c4 + 1]), 0.f);
                    v.z = fmaxf(fmaf(v.z, saff[c4 + 2], saff[16 + c4 + 2]), 0.f);
                    v.w = fmaxf(fmaf(v.w, saff[c4 + 3], saff[16 + c4 + 3]), 0.f);
                }
            }
            xs[(c4 + 0) * 132 + r] = v.x;
            xs[(c4 + 1) * 132 + r] = v.y;
            xs[(c4 + 2) * 132 + r] = v.z;
            xs[(c4 + 3) * 132 + r] = v.w;
        }
        __syncthreads();

        // ---- accumulate: per (c): 1 scalar W LDS (broadcast) + 2 LDS.128 x ----
        const float* wk = Ws + k * 256 + tx;
#pragma unroll
        for (int c = 0; c < 16; c++) {
            float wv = wk[c * 16];
            const float* xc = xs + c * 132 + ty * 8;
            float4 xa = *(const float4*)(xc);
            float4 xb = *(const float4*)(xc + 4);
            acc[0] = fmaf(xa.x, wv, acc[0]);
            acc[1] = fmaf(xa.y, wv, acc[1]);
            acc[2] = fmaf(xa.z, wv, acc[2]);
            acc[3] = fmaf(xa.w, wv, acc[3]);
            acc[4] = fmaf(xb.x, wv, acc[4]);
            acc[5] = fmaf(xb.y, wv, acc[5]);
            acc[6] = fmaf(xb.z, wv, acc[6]);
            acc[7] = fmaf(xb.w, wv, acc[7]);
        }
        __syncthreads();
    }

    // ---- write y + BN statistics ----
    float ps = 0.f, pq = 0.f;
#pragma unroll
    for (int j = 0; j < 8; j++) {
        int gr = row0 + ty * 8 + j;
        if (gr < N) {
            y[gr * 16 + tx] = acc[j];
            ps += acc[j];
            pq += acc[j] * acc[j];
        }
    }
    float* red = xs;   // reuse (>=512 floats available)
    red[ty * 16 + tx] = ps;
    red[256 + ty * 16 + tx] = pq;
    __syncthreads();
    if (ty == 0) {
        float s = 0.f, q = 0.f;
#pragma unroll
        for (int j = 0; j < 16; j++) {
            s += red[j * 16 + tx];
            q += red[256 + j * 16 + tx];
        }
        int base = (LAYER == 0) ? 0 : 32;
        atomicAdd(&g_stats[base + tx], s);
        atomicAdd(&g_stats[base + 16 + tx], q);
    }
}

// mean/var -> affine scale/shift
__global__ void finalize_kernel(const float* __restrict__ g,
                                const float* __restrict__ b,
                                int base, float invN)
{
    int c = threadIdx.x;
    if (c < 16) {
        float mu  = g_stats[base + c] * invN;
        float var = g_stats[base + 16 + c] * invN - mu * mu;
        float s   = g[c] * rsqrtf(var + CEPS);
        g_aff[base + c]      = s;
        g_aff[base + 16 + c] = b[c] - mu * s;
    }
}

// h1 = relu(bn1(y1)) scattered + (feat2 @ Wobo + bobo) scattered (segment_sum)
__global__ __launch_bounds__(256) void fuse_kernel(
    const float* __restrict__ y1, const float* __restrict__ f2,
    const float* __restrict__ Wobo, const float* __restrict__ bobo,
    const int* __restrict__ seg, int N)
{
    __shared__ float Wo[256];
    __shared__ float saff[32];
    int tid = threadIdx.x;
    Wo[tid] = Wobo[tid];
    if (tid < 32) saff[tid] = g_aff[32 + tid];
    __syncthreads();

    int tx = tid & 15, ty = tid >> 4;
    int n = blockIdx.x * 16 + ty;
    if (n >= N) return;   // N % 16 == 0 -> group-uniform

    float h = fmaxf(fmaf(y1[n * 16 + tx], saff[tx], saff[16 + tx]), 0.f);
    atomicAdd(&g_merged[seg[n] * 16 + tx], h);

    float f = f2[n * 16 + tx];
    float accv = bobo[tx];
    unsigned hm = 0xFFFFu << ((ty & 1) * 16);
#pragma unroll
    for (int c = 0; c < 16; c++)
        accv = fmaf(__shfl_sync(hm, f, c, 16), Wo[c * 16 + tx], accv);
    atomicAdd(&g_merged[seg[N + n] * 16 + tx], accv);
}

// out[u,:] = merged[u,:] @ Wf + bf   (one warp per row, float4 per lane)
__global__ __launch_bounds__(256) void out_kernel(
    const float* __restrict__ Wf, const float* __restrict__ bf,
    float* __restrict__ out, int U)
{
    __shared__ float Wfs[16 * 128];
    int tid = threadIdx.x;
    for (int i = tid; i < 2048; i += 256) Wfs[i] = Wf[i];
    __syncthreads();

    int lane = tid & 31, w = tid >> 5;
    int u = blockIdx.x * 8 + w;
    if (u >= U) return;   // warp-uniform

    float mv = g_merged[u * 16 + (lane & 15)];
    float4 accv = *(const float4*)(bf + lane * 4);
#pragma unroll
    for (int c = 0; c < 16; c++) {
        float xv = __shfl_sync(0xffffffffu, mv, c, 16);
        float4 wv = *(const float4*)&Wfs[c * 128 + lane * 4];
        accv.x = fmaf(xv, wv.x, accv.x);
        accv.y = fmaf(xv, wv.y, accv.y);
        accv.z = fmaf(xv, wv.z, accv.z);
        accv.w = fmaf(xv, wv.w, accv.w);
    }
    *(float4*)(out + u * 128 + lane * 4) = accv;
}

extern "C" void kernel_launch(void* const* d_in, const int* in_sizes, int n_in,
                              void* d_out, int out_size)
{
    const float* vox  = (const float*)d_in[0];
    const float* f2   = (const float*)d_in[1];
    const float* W0   = (const float*)d_in[2];
    const float* g0   = (const float*)d_in[3];
    const float* b0   = (const float*)d_in[4];
    const float* W1   = (const float*)d_in[5];
    const float* g1   = (const float*)d_in[6];
    const float* b1   = (const float*)d_in[7];
    const float* Wobo = (const float*)d_in[8];
    const float* bobo = (const float*)d_in[9];
    const float* Wf   = (const float*)d_in[10];
    const float* bf   = (const float*)d_in[11];
    const int*   nbr  = (const int*)d_in[12];
    const int*   seg  = (const int*)d_in[13];

    int N = in_sizes[0] / 16;
    int U = out_size / 128;

    void *p_stats, *p_merged, *p_y0, *p_y1;
    cudaGetSymbolAddress(&p_stats,  g_stats);
    cudaGetSymbolAddress(&p_merged, g_merged);
    cudaGetSymbolAddress(&p_y0,     g_y0);
    cudaGetSymbolAddress(&p_y1,     g_y1);

    cudaMemsetAsync(p_stats,  0, 64 * sizeof(float));
    cudaMemsetAsync(p_merged, 0, (size_t)U * 16 * sizeof(float));

    int cblocks = (N + 127) / 128;
    float invN = 1.0f / (float)N;

    conv_kernel<0><<<cblocks, 256>>>(vox, nbr, W0, (float*)p_y0, N);
    finalize_kernel<<<1, 16>>>(g0, b0, 0, invN);
    conv_kernel<1><<<cblocks, 256>>>((const float*)p_y0, nbr, W1, (float*)p_y1, N);
    finalize_kernel<<<1, 16>>>(g1, b1, 32, invN);
    fuse_kernel<<<(N + 15) / 16, 256>>>((const float*)p_y1, f2, Wobo, bobo, seg, N);
    out_kernel<<<(U + 7) / 8, 256>>>(Wf, bf, (float*)d_out, U);
}

// round 2
// speedup vs baseline: 1.0559x; 1.0559x over previous
#include <cuda_runtime.h>

#define CEPS 1e-3f

// scratch (allocation-free rule: __device__ globals)
__device__ float g_y0[100000 * 16];
__device__ float g_y1[100000 * 16];
__device__ float g_merged[200000 * 16];
__device__ float g_stats[64];   // [0:16) sum0, [16:32) sq0, [32:48) sum1, [48:64) sq1

// ---------------------------------------------------------------------------
// Submanifold 3x3x3 conv: y[n,o] = sum_k sum_c x[nbr[n,k],c] * W[k,c,o]
// Block: 256 threads -> 128 rows x 16 out-ch.  Thread: 8 rows x 1 ch.
// Neighbor table staged to SMEM (coalesced). Gather tile + W slice are
// double-buffered: stage k+1 while computing k, one sync per k.
// LAYER==1 computes the layer-0 BN affine from g_stats in the prologue and
// applies BN+ReLU to gathered values on the fly (missing neighbors stay 0).
// Epilogue accumulates per-channel sum / sumsq into g_stats.
// ---------------------------------------------------------------------------
template <int LAYER>
__global__ __launch_bounds__(256) void conv_kernel(
    const float* __restrict__ x, const int* __restrict__ nbr,
    const float* __restrict__ W, float* __restrict__ y,
    const float* __restrict__ g, const float* __restrict__ b,
    int N, float invN)
{
    __shared__ int   snbr[128 * 27];      // 13.8 KB
    __shared__ float xs[2][16 * 132];     // 16.9 KB, transposed [c][row]
    __shared__ float wk[2][256];          //  2.0 KB, per-k [c][o]
    __shared__ float saff[32];

    int tid = threadIdx.x;
    int row0 = blockIdx.x * 128;

    // stage neighbor table, coalesced
    int lim = (N - row0) * 27;
    for (int i = tid; i < 128 * 27; i += 256)
        snbr[i] = (i < lim) ? nbr[row0 * 27 + i] : -1;

    if (LAYER == 1 && tid < 16) {
        float mu  = g_stats[tid] * invN;
        float var = g_stats[16 + tid] * invN - mu * mu;
        float s   = g[tid] * rsqrtf(var + CEPS);
        saff[tid]      = s;
        saff[16 + tid] = b[tid] - mu * s;
    }

    int tx = tid & 15;    // output channel
    int ty = tid >> 4;    // row group (8 rows)

    float acc[8];
#pragma unroll
    for (int j = 0; j < 8; j++) acc[j] = 0.f;

    __syncthreads();

    // ---- staging helper (macro-style via lambda) ----
    auto stage = [&](int k, int buf) {
        wk[buf][tid] = W[k * 256 + tid];
#pragma unroll
        for (int i = 0; i < 2; i++) {
            int e  = tid + i * 256;     // 0..511 -> (row, c-quad)
            int r  = e >> 2;            // 0..127
            int c4 = (e & 3) * 4;
            int id = snbr[r * 27 + k];
            float4 v = make_float4(0.f, 0.f, 0.f, 0.f);
            if (id >= 0) {
                v = *(const float4*)(x + id * 16 + c4);
                if (LAYER == 1) {
                    v.x = fmaxf(fmaf(v.x, saff[c4 + 0], saff[16 + c4 + 0]), 0.f);
                    v.y = fmaxf(fmaf(v.y, saff[c4 + 1], saff[16 + c4 + 1]), 0.f);
                    v.z = fmaxf(fmaf(v.z, saff[c4 + 2], saff[16 + c4 + 2]), 0.f);
                    v.w = fmaxf(fmaf(v.w, saff[c4 + 3], saff[16 + c4 + 3]), 0.f);
                }
            }
            xs[buf][(c4 + 0) * 132 + r] = v.x;
            xs[buf][(c4 + 1) * 132 + r] = v.y;
            xs[buf][(c4 + 2) * 132 + r] = v.z;
            xs[buf][(c4 + 3) * 132 + r] = v.w;
        }
    };

    stage(0, 0);
    __syncthreads();

    for (int k = 0; k < 27; k++) {
        int cur = k & 1;
        if (k < 26) stage(k + 1, cur ^ 1);

        const float* wkc = wk[cur] + tx;
#pragma unroll
        for (int c = 0; c < 16; c++) {
            float wv = wkc[c * 16];
            const float* xc = xs[cur] + c * 132 + ty * 8;
            float4 xa = *(const float4*)(xc);
            float4 xb = *(const float4*)(xc + 4);
            acc[0] = fmaf(xa.x, wv, acc[0]);
            acc[1] = fmaf(xa.y, wv, acc[1]);
            acc[2] = fmaf(xa.z, wv, acc[2]);
            acc[3] = fmaf(xa.w, wv, acc[3]);
            acc[4] = fmaf(xb.x, wv, acc[4]);
            acc[5] = fmaf(xb.y, wv, acc[5]);
            acc[6] = fmaf(xb.z, wv, acc[6]);
            acc[7] = fmaf(xb.w, wv, acc[7]);
        }
        __syncthreads();
    }

    // ---- write y + BN statistics ----
    float ps = 0.f, pq = 0.f;
#pragma unroll
    for (int j = 0; j < 8; j++) {
        int gr = row0 + ty * 8 + j;
        if (gr < N) {
            y[gr * 16 + tx] = acc[j];
            ps += acc[j];
            pq += acc[j] * acc[j];
        }
    }
    float* red = xs[0];
    red[ty * 16 + tx] = ps;
    red[256 + ty * 16 + tx] = pq;
    __syncthreads();
    if (ty == 0) {
        float s = 0.f, q = 0.f;
#pragma unroll
        for (int j = 0; j < 16; j++) {
            s += red[j * 16 + tx];
            q += red[256 + j * 16 + tx];
        }
        int base = (LAYER == 0) ? 0 : 32;
        atomicAdd(&g_stats[base + tx], s);
        atomicAdd(&g_stats[base + 16 + tx], q);
    }
}

// h1 = relu(bn1(y1)) scattered + (feat2 @ Wobo + bobo) scattered (segment_sum)
__global__ __launch_bounds__(256) void fuse_kernel(
    const float* __restrict__ y1, const float* __restrict__ f2,
    const float* __restrict__ Wobo, const float* __restrict__ bobo,
    const float* __restrict__ g1, const float* __restrict__ b1,
    const int* __restrict__ seg, int N, float invN)
{
    __shared__ float Wo[256];
    __shared__ float saff[32];
    int tid = threadIdx.x;
    Wo[tid] = Wobo[tid];
    if (tid < 16) {
        float mu  = g_stats[32 + tid] * invN;
        float var = g_stats[48 + tid] * invN - mu * mu;
        float s   = g1[tid] * rsqrtf(var + CEPS);
        saff[tid]      = s;
        saff[16 + tid] = b1[tid] - mu * s;
    }
    __syncthreads();

    int tx = tid & 15, ty = tid >> 4;
    int n = blockIdx.x * 16 + ty;
    if (n >= N) return;   // N % 16 == 0 -> group-uniform

    float h = fmaxf(fmaf(y1[n * 16 + tx], saff[tx], saff[16 + tx]), 0.f);
    atomicAdd(&g_merged[seg[n] * 16 + tx], h);

    float f = f2[n * 16 + tx];
    float accv = bobo[tx];
    unsigned hm = 0xFFFFu << ((ty & 1) * 16);
#pragma unroll
    for (int c = 0; c < 16; c++)
        accv = fmaf(__shfl_sync(hm, f, c, 16), Wo[c * 16 + tx], accv);
    atomicAdd(&g_merged[seg[N + n] * 16 + tx], accv);
}

// out[u,:] = merged[u,:] @ Wf + bf   (one warp per row, float4 per lane)
__global__ __launch_bounds__(256) void out_kernel(
    const float* __restrict__ Wf, const float* __restrict__ bf,
    float* __restrict__ out, int U)
{
    __shared__ float Wfs[16 * 128];
    int tid = threadIdx.x;
    for (int i = tid; i < 2048; i += 256) Wfs[i] = Wf[i];
    __syncthreads();

    int lane = tid & 31, w = tid >> 5;
    int u = blockIdx.x * 8 + w;
    if (u >= U) return;   // warp-uniform

    float mv = g_merged[u * 16 + (lane & 15)];
    float4 accv = *(const float4*)(bf + lane * 4);
#pragma unroll
    for (int c = 0; c < 16; c++) {
        float xv = __shfl_sync(0xffffffffu, mv, c, 16);
        float4 wv = *(const float4*)&Wfs[c * 128 + lane * 4];
        accv.x = fmaf(xv, wv.x, accv.x);
        accv.y = fmaf(xv, wv.y, accv.y);
        accv.z = fmaf(xv, wv.z, accv.z);
        accv.w = fmaf(xv, wv.w, accv.w);
    }
    *(float4*)(out + u * 128 + lane * 4) = accv;
}

extern "C" void kernel_launch(void* const* d_in, const int* in_sizes, int n_in,
                              void* d_out, int out_size)
{
    const float* vox  = (const float*)d_in[0];
    const float* f2   = (const float*)d_in[1];
    const float* W0   = (const float*)d_in[2];
    const float* g0   = (const float*)d_in[3];
    const float* b0   = (const float*)d_in[4];
    const float* W1   = (const float*)d_in[5];
    const float* g1   = (const float*)d_in[6];
    const float* b1   = (const float*)d_in[7];
    const float* Wobo = (const float*)d_in[8];
    const float* bobo = (const float*)d_in[9];
    const float* Wf   = (const float*)d_in[10];
    const float* bf   = (const float*)d_in[11];
    const int*   nbr  = (const int*)d_in[12];
    const int*   seg  = (const int*)d_in[13];

    int N = in_sizes[0] / 16;
    int U = out_size / 128;

    void *p_stats, *p_merged, *p_y0, *p_y1;
    cudaGetSymbolAddress(&p_stats,  g_stats);
    cudaGetSymbolAddress(&p_merged, g_merged);
    cudaGetSymbolAddress(&p_y0,     g_y0);
    cudaGetSymbolAddress(&p_y1,     g_y1);

    cudaMemsetAsync(p_stats,  0, 64 * sizeof(float));
    cudaMemsetAsync(p_merged, 0, (size_t)U * 16 * sizeof(float));

    int cblocks = (N + 127) / 128;
    float invN = 1.0f / (float)N;

    conv_kernel<0><<<cblocks, 256>>>(vox, nbr, W0, (float*)p_y0,
                                     g0, b0, N, invN);
    conv_kernel<1><<<cblocks, 256>>>((const float*)p_y0, nbr, W1, (float*)p_y1,
                                     g1, b1, N, invN);
    fuse_kernel<<<(N + 15) / 16, 256>>>((const float*)p_y1, f2, Wobo, bobo,
                                        g1, b1, seg, N, invN);
    out_kernel<<<(U + 7) / 8, 256>>>(Wf, bf, (float*)d_out, U);
}